// round 15
// baseline (speedup 1.0000x reference)
#include <cuda_runtime.h>
#include <cuda_fp16.h>
#include <cstdint>

typedef unsigned int u32;
typedef unsigned long long u64;

#define E_NODES 1000000
#define NTILES ((E_NODES + 127) / 128)
#define PGRID 304

// Scratch activations (fp16) + prepacked weights (alloc-free rule)
__device__ __half g_bufA[(size_t)E_NODES * 64];
__device__ __half g_bufB[(size_t)E_NODES * 64];
__device__ __half g_WR[3 * 64 * 320];                // [l][n][kperm2]  fp16
__device__ __align__(16) u32 g_B0[4 * 8 * 32 * 2];   // l0 frag-packed B (fp16)
__device__ __align__(16) __half g_C1[32 * 64];       // cls W1 frag tile (fp16)

// ---------------------------------------------------------------------------
// helpers
// ---------------------------------------------------------------------------
__device__ __forceinline__ u32 s2u(const void* p) {
    u32 a;
    asm("{.reg .u64 t; cvta.to.shared.u64 t,%1; cvt.u32.u64 %0,t;}" : "=r"(a) : "l"(p));
    return a;
}
__device__ __forceinline__ u32 swz(u32 b) { return b ^ ((b >> 3) & 0x70); }

__device__ __forceinline__ void ldmx4(u32* r, u32 addr) {
    asm volatile("ldmatrix.sync.aligned.m8n8.x4.shared.b16 {%0,%1,%2,%3},[%4];"
                 : "=r"(r[0]), "=r"(r[1]), "=r"(r[2]), "=r"(r[3]) : "r"(addr));
}
__device__ __forceinline__ void mma_h(float* d, const u32* a, u32 b0, u32 b1) {
    asm volatile(
        "mma.sync.aligned.m16n8k16.row.col.f32.f16.f16.f32 "
        "{%0,%1,%2,%3},{%4,%5,%6,%7},{%8,%9},{%0,%1,%2,%3};"
        : "+f"(d[0]), "+f"(d[1]), "+f"(d[2]), "+f"(d[3])
        : "r"(a[0]), "r"(a[1]), "r"(a[2]), "r"(a[3]), "r"(b0), "r"(b1));
}

__device__ __forceinline__ u32 bits2h(__half2 v) {
    u32 u; __builtin_memcpy(&u, &v, 4); return u;
}
__device__ __forceinline__ __half2 h2(u32 u) {
    __half2 v; __builtin_memcpy(&v, &u, 4); return v;
}
__device__ __forceinline__ u32 habsd(u32 a, u32 c) {
    return bits2h(__habs2(__hsub2(h2(a), h2(c))));
}
__device__ __forceinline__ u32 hsum(u32 a, u32 c) {
    return bits2h(__hadd2(h2(a), h2(c)));
}
// split (a,b) fp32 pair into hi/lo fp16x2 packs
__device__ __forceinline__ void split2h(float a, float b, u32& h, u32& l) {
    __half2 hh = __floats2half2_rn(a, b);
    float ra = a - __half2float(__low2half(hh));
    float rb = b - __half2float(__high2half(hh));
    __half2 ll = __floats2half2_rn(ra, rb);
    h = bits2h(hh); l = bits2h(ll);
}

// ---------------------------------------------------------------------------
// weight prep:
//  - mids: transpose to [n][k], K-PERM v2 (paired-uint4 gather layout)
//  - l0:   frag-packed B (logical k), zero-pad K 55->64
//  - cls:  cw1 -> [32 n][64 k] swizzled frag tile (4 KB)
// ---------------------------------------------------------------------------
__global__ void prep_w(const float* __restrict__ w0, const float* __restrict__ wr,
                       const float* __restrict__ cw1)
{
    int i = blockIdx.x * blockDim.x + threadIdx.x;
    if (i < 1024) {
        int lane = i & 31, nq = (i >> 5) & 7, j = (i >> 8) & 3;
        int g = lane >> 2, t = lane & 3, n = nq * 8 + g;
        int ks[4] = {16 * j + 2 * t, 16 * j + 2 * t + 1,
                     16 * j + 2 * t + 8, 16 * j + 2 * t + 9};
        __half b[4];
#pragma unroll
        for (int q = 0; q < 4; q++) {
            int k = ks[q];
            float v = (k < 55) ? w0[k * 64 + n] : 0.f;
            b[q] = __float2half_rn(v);
        }
        g_B0[i * 2]     = bits2h(__halves2half2(b[0], b[1]));
        g_B0[i * 2 + 1] = bits2h(__halves2half2(b[2], b[3]));
    }
    if (i < 2048) {
        int n = i >> 6, k = i & 63;
        float v = cw1[k * 32 + n];
        *(__half*)((char*)g_C1 + swz((u32)(n * 128 + k * 2))) = __float2half_rn(v);
    }
    if (i < 3 * 64 * 320) {
        int l = i / (64 * 320), r = i % (64 * 320);
        int n = r / 320, k = r % 320;
        float v = wr[(size_t)l * 320 * 64 + (size_t)k * 64 + n];
        // k-perm v2 within each 64-half segment: logical ls -> eff E
        int ls = k & 63;
        int p = ls >> 5, q5 = ls & 31, tt = q5 >> 3, q = q5 & 7;
        int E = (p << 5) + ((q >> 2) << 4) + 2 * tt + (q & 1) + (((q >> 1) & 1) << 3);
        int kp = (k & ~63) | E;
        g_WR[((size_t)l * 64 + n) * 320 + kp] = __float2half_rn(v);
    }
}

// ===========================================================================
// Layer 0 (C=11): persistent, barrier-free, warp-private frag-packed A
// fp32 input -> hi/lo 2-term; fp16 output  (unchanged, proven)
// ===========================================================================
constexpr int L0_B0 = 0;
constexpr int L0_A  = 8192;
constexpr int SMEM_L0 = L0_A + 8 * 4096;  // 40960

__global__ __launch_bounds__(256, 2)
void mesh_l0(const float* __restrict__ xin, const int* __restrict__ nbr,
             const u32* __restrict__ B0, const float* __restrict__ bias,
             const float* __restrict__ lng, const float* __restrict__ lnb,
             __half* __restrict__ out)
{
    extern __shared__ char smc[];
    const int tid = threadIdx.x, wid = tid >> 5, lane = tid & 31;

    for (int i = tid; i < 512; i += 256)
        ((uint4*)(smc + L0_B0))[i] = ((const uint4*)B0)[i];
    __syncthreads();

    char* Aw = smc + L0_A + wid * 4096;
    const int  w     = lane >> 1;
    const int  half_ = lane & 1;
    const int  g = lane >> 2, t = lane & 3;

    for (int tile = blockIdx.x; tile < NTILES; tile += gridDim.x) {
        const int node0 = tile * 128;
        const int node  = node0 + wid * 16 + w;
        const bool valid = node < E_NODES;

        __syncwarp();

        auto wrA = [&](int k, float v) {
            __half hh = __float2half_rn(v);
            __half ll = __float2half_rn(v - __half2float(hh));
            int j = k >> 4, kk = k & 15;
            int pair = kk >> 3, tt = (kk >> 1) & 3, ii = kk & 1;
            int reg = pair * 2 + (w >> 3);
            u32 off = (u32)(((j * 32 + (w & 7) * 4 + tt) << 4) + reg * 4 + ii * 2);
            *(__half*)(Aw + off)        = hh;
            *(__half*)(Aw + 2048 + off) = ll;
        };

        if (valid) {
            int4 nb = ((const int4*)nbr)[node];
            if (half_ == 0) {
                const float* xr = xin + (size_t)node * 11;
                const float* A_ = xin + (size_t)nb.x * 11;
                const float* C_ = xin + (size_t)nb.z * 11;
#pragma unroll
                for (int ch = 0; ch < 11; ch++) {
                    wrA(ch, xr[ch]);
                    float a = A_[ch], c = C_[ch];
                    wrA(11 + ch, fabsf(a - c));
                    wrA(22 + ch, a + c);
                }
            } else {
                const float* B_ = xin + (size_t)nb.y * 11;
                const float* D_ = xin + (size_t)nb.w * 11;
#pragma unroll
                for (int ch = 0; ch < 11; ch++) {
                    float b = B_[ch], d = D_[ch];
                    wrA(33 + ch, fabsf(b - d));
                    wrA(44 + ch, b + d);
                }
#pragma unroll
                for (int k = 55; k < 64; k++) wrA(k, 0.f);
            }
        }
        __syncwarp();

        float acc[8][4];
#pragma unroll
        for (int q = 0; q < 8; q++)
#pragma unroll
            for (int c = 0; c < 4; c++) acc[q][c] = 0.f;

#pragma unroll
        for (int j = 0; j < 4; j++) {
            uint4 avh = *(const uint4*)(Aw + (j * 32 + lane) * 16);
            uint4 avl = *(const uint4*)(Aw + 2048 + (j * 32 + lane) * 16);
            u32 ah[4] = {avh.x, avh.y, avh.z, avh.w};
            u32 al[4] = {avl.x, avl.y, avl.z, avl.w};
#pragma unroll
            for (int nq = 0; nq < 8; nq++) {
                uint2 bh = *(const uint2*)(smc + L0_B0 + (size_t)((j * 8 + nq) * 32 + lane) * 8);
                mma_h(acc[nq], ah, bh.x, bh.y);
                mma_h(acc[nq], al, bh.x, bh.y);
            }
        }

#pragma unroll
        for (int hf = 0; hf < 2; hf++) {
            int row = node0 + wid * 16 + g + 8 * hf;
            bool vv = row < E_NODES;
            float tv[16];
            float part = 0.f;
#pragma unroll
            for (int nq = 0; nq < 8; nq++) {
                int c = 8 * nq + 2 * t;
                float2 b2 = *(const float2*)(bias + c);
                tv[2 * nq]     = acc[nq][2 * hf]     + b2.x;
                tv[2 * nq + 1] = acc[nq][2 * hf + 1] + b2.y;
                part += tv[2 * nq] + tv[2 * nq + 1];
            }
            part += __shfl_xor_sync(0xFFFFFFFFu, part, 1);
            part += __shfl_xor_sync(0xFFFFFFFFu, part, 2);
            float mu = part * (1.f / 64.f);
            float vp = 0.f;
#pragma unroll
            for (int i = 0; i < 16; i++) { float d = tv[i] - mu; vp += d * d; }
            vp += __shfl_xor_sync(0xFFFFFFFFu, vp, 1);
            vp += __shfl_xor_sync(0xFFFFFFFFu, vp, 2);
            float rs = rsqrtf(vp * (1.f / 64.f) + 1e-5f);
#pragma unroll
            for (int nq = 0; nq < 8; nq++) {
                int c = 8 * nq + 2 * t;
                float2 g2  = *(const float2*)(lng + c);
                float2 lb2 = *(const float2*)(lnb + c);
                float y0 = fmaxf((tv[2 * nq]     - mu) * rs * g2.x + lb2.x, 0.f);
                float y1 = fmaxf((tv[2 * nq + 1] - mu) * rs * g2.y + lb2.y, 0.f);
                if (vv) *(__half2*)(out + (size_t)row * 64 + c) = __floats2half2_rn(y0, y1);
            }
        }
    }
}

// ===========================================================================
// 64-ch layers: persistent, barrier-free, paired-uint4 gather (k-perm v2)
// 256 threads, 8 warps, warp = 16 nodes, tile = 128 nodes
// CLS: HMMA head (2-term split) from acc frags
// ===========================================================================
constexpr int NOFF_B  = 8192;                // C1 frag tile lives at 0 (4 KB)
constexpr int NSMEM   = NOFF_B + 5 * 8192;   // 49152

template <bool CLS>
__global__ __launch_bounds__(256, 2)
void mesh_fast(const __half* __restrict__ xin, const int* __restrict__ nbr,
               const __half* __restrict__ Wt,          // [64][320] (k-perm2) fp16
               const float* __restrict__ bias, const float* __restrict__ lng,
               const float* __restrict__ lnb,
               const __half* __restrict__ c1t,         // cls frag tile (4 KB)
               const float* __restrict__ cb1,
               const float* __restrict__ cw2, const float* __restrict__ cb2,
               __half* __restrict__ outh, float* __restrict__ outf)
{
    extern __shared__ char smc[];
    const int tid = threadIdx.x, wid = tid >> 5, lane = tid & 31;

    // ---- stage B once: 5 segments, swizzled rows for ldmatrix (40 KB) ----
    for (int j = tid; j < 2560; j += 256) {
        int r = j >> 3, c = j & 7;
        int seg = r >> 6, nrow = r & 63;
        const char* src = (const char*)Wt + (size_t)nrow * 640 + seg * 128 + c * 16;
        char* dst = smc + NOFF_B + seg * 8192;
        *(uint4*)(dst + swz((u32)(nrow * 128 + c * 16))) = *(const uint4*)src;
    }
    if (CLS) {
        for (int i = tid; i < 256; i += 256)
            ((uint4*)smc)[i] = ((const uint4*)c1t)[i];
    }
    __syncthreads();   // the ONLY block barrier

    const int g = lane >> 2, t = lane & 3, t4 = lane >> 3;

    auto bofs = [&](int pb, int k16) -> u32 {
        return swz((u32)(((2 * pb + (t4 >> 1)) * 8 + (lane & 7)) * 128
                         + k16 * 32 + ((t4 & 1) << 4)));
    };

    for (int tile = blockIdx.x; tile < NTILES; tile += gridDim.x) {
        const int node0 = tile * 128;
        const int base = node0 + wid * 16 + g;
        const int row0 = base, row1 = base + 8;
        const bool v0 = row0 < E_NODES, v1 = row1 < E_NODES;
        const int rr0 = v0 ? row0 : 0, rr1 = v1 ? row1 : 0;

        const int4 nb0 = ((const int4*)nbr)[rr0];
        const int4 nb1 = ((const int4*)nbr)[rr1];

        float acc[8][4];
#pragma unroll
        for (int q = 0; q < 8; q++)
#pragma unroll
            for (int c = 0; c < 4; c++) acc[q][c] = 0.f;

        auto run_seg = [&](int seg, int k16, const u32* ah) {
            u32 bh[16];
            u32 bb = s2u(smc + NOFF_B + seg * 8192);
#pragma unroll
            for (int pb = 0; pb < 4; pb++)
                ldmx4(bh + 4 * pb, bb + bofs(pb, k16));
#pragma unroll
            for (int nq = 0; nq < 8; nq++)
                mma_h(acc[nq], ah, bh[2 * nq], bh[2 * nq + 1]);
        };

        // ---- phase 0: x (seg 0) — one uint4 covers two k16 blocks ----
#pragma unroll
        for (int p = 0; p < 2; p++) {
            const int fo = 32 * p + 8 * t;
            uint4 x0 = *(const uint4*)(xin + (size_t)rr0 * 64 + fo);
            uint4 x1 = *(const uint4*)(xin + (size_t)rr1 * 64 + fo);
            u32 aA[4] = {x0.x, x1.x, x0.y, x1.y};
            run_seg(0, 2 * p, aA);
            u32 aB[4] = {x0.z, x1.z, x0.w, x1.w};
            run_seg(0, 2 * p + 1, aB);
        }

        // ---- phases 1,2: neighbor pairs (segs 1,2 and 3,4) ----
#pragma unroll
        for (int ph = 0; ph < 2; ph++) {
            const int sd = ph ? 3 : 1;
            const int ia0 = ph ? nb0.y : nb0.x;
            const int ic0 = ph ? nb0.w : nb0.z;
            const int ia1 = ph ? nb1.y : nb1.x;
            const int ic1 = ph ? nb1.w : nb1.z;
            const __half* A0 = xin + (size_t)ia0 * 64;
            const __half* C0 = xin + (size_t)ic0 * 64;
            const __half* A1 = xin + (size_t)ia1 * 64;
            const __half* C1_ = xin + (size_t)ic1 * 64;
#pragma unroll
            for (int p = 0; p < 2; p++) {
                const int fo = 32 * p + 8 * t;
                uint4 a0 = *(const uint4*)(A0 + fo);
                uint4 a1 = *(const uint4*)(A1 + fo);
                uint4 c0 = *(const uint4*)(C0 + fo);
                uint4 c1 = *(const uint4*)(C1_ + fo);
                u32 dA[4] = {habsd(a0.x, c0.x), habsd(a1.x, c1.x),
                             habsd(a0.y, c0.y), habsd(a1.y, c1.y)};
                run_seg(sd, 2 * p, dA);
                u32 dB[4] = {habsd(a0.z, c0.z), habsd(a1.z, c1.z),
                             habsd(a0.w, c0.w), habsd(a1.w, c1.w)};
                run_seg(sd, 2 * p + 1, dB);
                u32 sA[4] = {hsum(a0.x, c0.x), hsum(a1.x, c1.x),
                             hsum(a0.y, c0.y), hsum(a1.y, c1.y)};
                run_seg(sd + 1, 2 * p, sA);
                u32 sB[4] = {hsum(a0.z, c0.z), hsum(a1.z, c1.z),
                             hsum(a0.w, c0.w), hsum(a1.w, c1.w)};
                run_seg(sd + 1, 2 * p + 1, sB);
            }
        }

        // ---- epilogue: bias + LN + ReLU + residual, in registers ----
#pragma unroll
        for (int hf = 0; hf < 2; hf++) {
            const int row = hf ? row1 : row0;
            const bool v_ = hf ? v1 : v0;
            float tv[16];
            float part = 0.f;
#pragma unroll
            for (int nq = 0; nq < 8; nq++) {
                int c = 8 * nq + 2 * t;
                float2 b2 = *(const float2*)(bias + c);
                tv[2 * nq]     = acc[nq][2 * hf]     + b2.x;
                tv[2 * nq + 1] = acc[nq][2 * hf + 1] + b2.y;
                part += tv[2 * nq] + tv[2 * nq + 1];
            }
            part += __shfl_xor_sync(0xFFFFFFFFu, part, 1);
            part += __shfl_xor_sync(0xFFFFFFFFu, part, 2);
            float mu = part * (1.f / 64.f);
            float vp = 0.f;
#pragma unroll
            for (int i = 0; i < 16; i++) { float d = tv[i] - mu; vp += d * d; }
            vp += __shfl_xor_sync(0xFFFFFFFFu, vp, 1);
            vp += __shfl_xor_sync(0xFFFFFFFFu, vp, 2);
            float rsv = rsqrtf(vp * (1.f / 64.f) + 1e-5f);
#pragma unroll
            for (int nq = 0; nq < 8; nq++) {
                int c = 8 * nq + 2 * t;
                float2 g2  = *(const float2*)(lng + c);
                float2 lb2 = *(const float2*)(lnb + c);
                float2 xr  = __half22float2(*(const __half2*)(xin + (size_t)(v_ ? row : 0) * 64 + c));
                float y0 = fmaxf((tv[2 * nq]     - mu) * rsv * g2.x + lb2.x, 0.f) + xr.x;
                float y1 = fmaxf((tv[2 * nq + 1] - mu) * rsv * g2.y + lb2.y, 0.f) + xr.y;
                if (!CLS) {
                    if (v_) *(__half2*)(outh + (size_t)row * 64 + c) = __floats2half2_rn(y0, y1);
                } else {
                    acc[nq][2 * hf]     = y0;
                    acc[nq][2 * hf + 1] = y1;
                }
            }
        }

        if (CLS) {
            // ---- head GEMM z = y@cw1 + cb1 on HMMA (2-term split) ----
            float zacc[4][4];
#pragma unroll
            for (int nq = 0; nq < 4; nq++) {
                float b0 = __ldg(cb1 + 8 * nq + 2 * t);
                float b1 = __ldg(cb1 + 8 * nq + 2 * t + 1);
                zacc[nq][0] = b0; zacc[nq][1] = b1; zacc[nq][2] = b0; zacc[nq][3] = b1;
            }
            const u32 c1h = s2u(smc);
#pragma unroll
            for (int j = 0; j < 4; j++) {
                u32 ah[4], al[4];
                split2h(acc[2 * j][0],     acc[2 * j][1],     ah[0], al[0]);
                split2h(acc[2 * j][2],     acc[2 * j][3],     ah[1], al[1]);
                split2h(acc[2 * j + 1][0], acc[2 * j + 1][1], ah[2], al[2]);
                split2h(acc[2 * j + 1][2], acc[2 * j + 1][3], ah[3], al[3]);
                u32 bh[8];
#pragma unroll
                for (int pb = 0; pb < 2; pb++)
                    ldmx4(bh + 4 * pb, c1h + bofs(pb, j));
#pragma unroll
                for (int nq = 0; nq < 4; nq++) {
                    mma_h(zacc[nq], ah, bh[2 * nq], bh[2 * nq + 1]);
                    mma_h(zacc[nq], al, bh[2 * nq], bh[2 * nq + 1]);
                }
            }
            float p0 = 0.f, p1 = 0.f;
#pragma unroll
            for (int nq = 0; nq < 4; nq++) {
                float w0 = __ldg(cw2 + 8 * nq + 2 * t);
                float w1 = __ldg(cw2 + 8 * nq + 2 * t + 1);
                p0 += fmaxf(zacc[nq][0], 0.f) * w0 + fmaxf(zacc[nq][1], 0.f) * w1;
                p1 += fmaxf(zacc[nq][2], 0.f) * w0 + fmaxf(zacc[nq][3], 0.f) * w1;
            }
            p0 += __shfl_xor_sync(0xFFFFFFFFu, p0, 1);
            p0 += __shfl_xor_sync(0xFFFFFFFFu, p0, 2);
            p1 += __shfl_xor_sync(0xFFFFFFFFu, p1, 1);
            p1 += __shfl_xor_sync(0xFFFFFFFFu, p1, 2);
            if (t == 0) {
                float c2 = __ldg(cb2);
                if (v0) outf[row0] = p0 + c2;
                if (v1) outf[row1] = p1 + c2;
            }
        }
    }
}

// ---------------------------------------------------------------------------

extern "C" void kernel_launch(void* const* d_in, const int* in_sizes, int n_in,
                              void* d_out, int out_size)
{
    const float* x      = (const float*)d_in[0];
    const int*   nbr    = (const int*)  d_in[1];
    const float* w0     = (const float*)d_in[2];
    const float* b0     = (const float*)d_in[3];
    const float* w_rest = (const float*)d_in[4];
    const float* b_rest = (const float*)d_in[5];
    const float* ln_g   = (const float*)d_in[6];
    const float* ln_b   = (const float*)d_in[7];
    const float* cw1    = (const float*)d_in[8];
    const float* cb1    = (const float*)d_in[9];
    const float* cw2    = (const float*)d_in[10];
    const float* cb2    = (const float*)d_in[11];
    float* out = (float*)d_out;

    __half *bufA, *bufB, *WRp, *C1p;
    u32 *B0p;
    cudaGetSymbolAddress((void**)&bufA, g_bufA);
    cudaGetSymbolAddress((void**)&bufB, g_bufB);
    cudaGetSymbolAddress((void**)&WRp, g_WR);
    cudaGetSymbolAddress((void**)&B0p, g_B0);
    cudaGetSymbolAddress((void**)&C1p, g_C1);

    cudaFuncSetAttribute(mesh_l0, cudaFuncAttributeMaxDynamicSharedMemorySize, SMEM_L0);
    cudaFuncSetAttribute(mesh_fast<false>, cudaFuncAttributeMaxDynamicSharedMemorySize, NSMEM);
    cudaFuncSetAttribute(mesh_fast<true>,  cudaFuncAttributeMaxDynamicSharedMemorySize, NSMEM);

    prep_w<<<240, 256>>>(w0, w_rest, cw1);

    mesh_l0<<<PGRID, 256, SMEM_L0>>>(x, nbr, B0p, b0, ln_g, ln_b, bufA);

    mesh_fast<false><<<PGRID, 256, NSMEM>>>(
        bufA, nbr, WRp, b_rest, ln_g + 64, ln_b + 64,
        nullptr, nullptr, nullptr, nullptr, bufB, nullptr);

    mesh_fast<false><<<PGRID, 256, NSMEM>>>(
        bufB, nbr, WRp + 64 * 320, b_rest + 64, ln_g + 128, ln_b + 128,
        nullptr, nullptr, nullptr, nullptr, bufA, nullptr);

    mesh_fast<true><<<PGRID, 256, NSMEM>>>(
        bufA, nbr, WRp + 2 * 64 * 320, b_rest + 128, ln_g + 192, ln_b + 192,
        C1p, cb1, cw2, cb2, nullptr, out);
}

// round 16
// speedup vs baseline: 1.0555x; 1.0555x over previous
#include <cuda_runtime.h>
#include <cuda_fp16.h>
#include <cstdint>

typedef unsigned int u32;
typedef unsigned long long u64;

#define E_NODES 1000000
#define NTILES ((E_NODES + 127) / 128)
#define PGRID_L0 304
#define PGRID_MID 456

// Scratch activations (fp16) + prepacked weights (alloc-free rule)
__device__ __half g_bufA[(size_t)E_NODES * 64];
__device__ __half g_bufB[(size_t)E_NODES * 64];
__device__ __half g_WR[3 * 64 * 320];                // [l][n][kperm2]  fp16
__device__ __align__(16) u32 g_B0[4 * 8 * 32 * 2];   // l0 frag-packed B (fp16)
__device__ __align__(16) __half g_C1[32 * 64];       // cls W1 frag tile (fp16)

// ---------------------------------------------------------------------------
// helpers
// ---------------------------------------------------------------------------
__device__ __forceinline__ u32 s2u(const void* p) {
    u32 a;
    asm("{.reg .u64 t; cvta.to.shared.u64 t,%1; cvt.u32.u64 %0,t;}" : "=r"(a) : "l"(p));
    return a;
}
__device__ __forceinline__ u32 swz(u32 b) { return b ^ ((b >> 3) & 0x70); }

__device__ __forceinline__ void ldmx4(u32* r, u32 addr) {
    asm volatile("ldmatrix.sync.aligned.m8n8.x4.shared.b16 {%0,%1,%2,%3},[%4];"
                 : "=r"(r[0]), "=r"(r[1]), "=r"(r[2]), "=r"(r[3]) : "r"(addr));
}
__device__ __forceinline__ void mma_h(float* d, const u32* a, u32 b0, u32 b1) {
    asm volatile(
        "mma.sync.aligned.m16n8k16.row.col.f32.f16.f16.f32 "
        "{%0,%1,%2,%3},{%4,%5,%6,%7},{%8,%9},{%0,%1,%2,%3};"
        : "+f"(d[0]), "+f"(d[1]), "+f"(d[2]), "+f"(d[3])
        : "r"(a[0]), "r"(a[1]), "r"(a[2]), "r"(a[3]), "r"(b0), "r"(b1));
}

__device__ __forceinline__ u32 bits2h(__half2 v) {
    u32 u; __builtin_memcpy(&u, &v, 4); return u;
}
__device__ __forceinline__ __half2 h2(u32 u) {
    __half2 v; __builtin_memcpy(&v, &u, 4); return v;
}
__device__ __forceinline__ u32 habsd(u32 a, u32 c) {
    return bits2h(__habs2(__hsub2(h2(a), h2(c))));
}
__device__ __forceinline__ u32 hsum(u32 a, u32 c) {
    return bits2h(__hadd2(h2(a), h2(c)));
}
// split (a,b) fp32 pair into hi/lo fp16x2 packs
__device__ __forceinline__ void split2h(float a, float b, u32& h, u32& l) {
    __half2 hh = __floats2half2_rn(a, b);
    float ra = a - __half2float(__low2half(hh));
    float rb = b - __half2float(__high2half(hh));
    __half2 ll = __floats2half2_rn(ra, rb);
    h = bits2h(hh); l = bits2h(ll);
}

// ---------------------------------------------------------------------------
// weight prep:
//  - mids: transpose to [n][k], K-PERM v2 (paired-uint4 gather layout)
//  - l0:   frag-packed B (logical k), zero-pad K 55->64
//  - cls:  cw1 -> [32 n][64 k] swizzled frag tile (4 KB)
// ---------------------------------------------------------------------------
__global__ void prep_w(const float* __restrict__ w0, const float* __restrict__ wr,
                       const float* __restrict__ cw1)
{
    int i = blockIdx.x * blockDim.x + threadIdx.x;
    if (i < 1024) {
        int lane = i & 31, nq = (i >> 5) & 7, j = (i >> 8) & 3;
        int g = lane >> 2, t = lane & 3, n = nq * 8 + g;
        int ks[4] = {16 * j + 2 * t, 16 * j + 2 * t + 1,
                     16 * j + 2 * t + 8, 16 * j + 2 * t + 9};
        __half b[4];
#pragma unroll
        for (int q = 0; q < 4; q++) {
            int k = ks[q];
            float v = (k < 55) ? w0[k * 64 + n] : 0.f;
            b[q] = __float2half_rn(v);
        }
        g_B0[i * 2]     = bits2h(__halves2half2(b[0], b[1]));
        g_B0[i * 2 + 1] = bits2h(__halves2half2(b[2], b[3]));
    }
    if (i < 2048) {
        int n = i >> 6, k = i & 63;
        float v = cw1[k * 32 + n];
        *(__half*)((char*)g_C1 + swz((u32)(n * 128 + k * 2))) = __float2half_rn(v);
    }
    if (i < 3 * 64 * 320) {
        int l = i / (64 * 320), r = i % (64 * 320);
        int n = r / 320, k = r % 320;
        float v = wr[(size_t)l * 320 * 64 + (size_t)k * 64 + n];
        // k-perm v2 within each 64-half segment: logical ls -> eff E
        int ls = k & 63;
        int p = ls >> 5, q5 = ls & 31, tt = q5 >> 3, q = q5 & 7;
        int E = (p << 5) + ((q >> 2) << 4) + 2 * tt + (q & 1) + (((q >> 1) & 1) << 3);
        int kp = (k & ~63) | E;
        g_WR[((size_t)l * 64 + n) * 320 + kp] = __float2half_rn(v);
    }
}

// ===========================================================================
// Layer 0 (C=11): persistent, barrier-free, warp-private frag-packed A
// fp32 input -> hi/lo 2-term; fp16 output  (unchanged, proven)
// ===========================================================================
constexpr int L0_B0 = 0;
constexpr int L0_A  = 8192;
constexpr int SMEM_L0 = L0_A + 8 * 4096;  // 40960

__global__ __launch_bounds__(256, 2)
void mesh_l0(const float* __restrict__ xin, const int* __restrict__ nbr,
             const u32* __restrict__ B0, const float* __restrict__ bias,
             const float* __restrict__ lng, const float* __restrict__ lnb,
             __half* __restrict__ out)
{
    extern __shared__ char smc[];
    const int tid = threadIdx.x, wid = tid >> 5, lane = tid & 31;

    for (int i = tid; i < 512; i += 256)
        ((uint4*)(smc + L0_B0))[i] = ((const uint4*)B0)[i];
    __syncthreads();

    char* Aw = smc + L0_A + wid * 4096;
    const int  w     = lane >> 1;
    const int  half_ = lane & 1;
    const int  g = lane >> 2, t = lane & 3;

    for (int tile = blockIdx.x; tile < NTILES; tile += gridDim.x) {
        const int node0 = tile * 128;
        const int node  = node0 + wid * 16 + w;
        const bool valid = node < E_NODES;

        __syncwarp();

        auto wrA = [&](int k, float v) {
            __half hh = __float2half_rn(v);
            __half ll = __float2half_rn(v - __half2float(hh));
            int j = k >> 4, kk = k & 15;
            int pair = kk >> 3, tt = (kk >> 1) & 3, ii = kk & 1;
            int reg = pair * 2 + (w >> 3);
            u32 off = (u32)(((j * 32 + (w & 7) * 4 + tt) << 4) + reg * 4 + ii * 2);
            *(__half*)(Aw + off)        = hh;
            *(__half*)(Aw + 2048 + off) = ll;
        };

        if (valid) {
            int4 nb = ((const int4*)nbr)[node];
            if (half_ == 0) {
                const float* xr = xin + (size_t)node * 11;
                const float* A_ = xin + (size_t)nb.x * 11;
                const float* C_ = xin + (size_t)nb.z * 11;
#pragma unroll
                for (int ch = 0; ch < 11; ch++) {
                    wrA(ch, xr[ch]);
                    float a = A_[ch], c = C_[ch];
                    wrA(11 + ch, fabsf(a - c));
                    wrA(22 + ch, a + c);
                }
            } else {
                const float* B_ = xin + (size_t)nb.y * 11;
                const float* D_ = xin + (size_t)nb.w * 11;
#pragma unroll
                for (int ch = 0; ch < 11; ch++) {
                    float b = B_[ch], d = D_[ch];
                    wrA(33 + ch, fabsf(b - d));
                    wrA(44 + ch, b + d);
                }
#pragma unroll
                for (int k = 55; k < 64; k++) wrA(k, 0.f);
            }
        }
        __syncwarp();

        float acc[8][4];
#pragma unroll
        for (int q = 0; q < 8; q++)
#pragma unroll
            for (int c = 0; c < 4; c++) acc[q][c] = 0.f;

#pragma unroll
        for (int j = 0; j < 4; j++) {
            uint4 avh = *(const uint4*)(Aw + (j * 32 + lane) * 16);
            uint4 avl = *(const uint4*)(Aw + 2048 + (j * 32 + lane) * 16);
            u32 ah[4] = {avh.x, avh.y, avh.z, avh.w};
            u32 al[4] = {avl.x, avl.y, avl.z, avl.w};
#pragma unroll
            for (int nq = 0; nq < 8; nq++) {
                uint2 bh = *(const uint2*)(smc + L0_B0 + (size_t)((j * 8 + nq) * 32 + lane) * 8);
                mma_h(acc[nq], ah, bh.x, bh.y);
                mma_h(acc[nq], al, bh.x, bh.y);
            }
        }

#pragma unroll
        for (int hf = 0; hf < 2; hf++) {
            int row = node0 + wid * 16 + g + 8 * hf;
            bool vv = row < E_NODES;
            float tv[16];
            float part = 0.f;
#pragma unroll
            for (int nq = 0; nq < 8; nq++) {
                int c = 8 * nq + 2 * t;
                float2 b2 = *(const float2*)(bias + c);
                tv[2 * nq]     = acc[nq][2 * hf]     + b2.x;
                tv[2 * nq + 1] = acc[nq][2 * hf + 1] + b2.y;
                part += tv[2 * nq] + tv[2 * nq + 1];
            }
            part += __shfl_xor_sync(0xFFFFFFFFu, part, 1);
            part += __shfl_xor_sync(0xFFFFFFFFu, part, 2);
            float mu = part * (1.f / 64.f);
            float vp = 0.f;
#pragma unroll
            for (int i = 0; i < 16; i++) { float d = tv[i] - mu; vp += d * d; }
            vp += __shfl_xor_sync(0xFFFFFFFFu, vp, 1);
            vp += __shfl_xor_sync(0xFFFFFFFFu, vp, 2);
            float rs = rsqrtf(vp * (1.f / 64.f) + 1e-5f);
#pragma unroll
            for (int nq = 0; nq < 8; nq++) {
                int c = 8 * nq + 2 * t;
                float2 g2  = *(const float2*)(lng + c);
                float2 lb2 = *(const float2*)(lnb + c);
                float y0 = fmaxf((tv[2 * nq]     - mu) * rs * g2.x + lb2.x, 0.f);
                float y1 = fmaxf((tv[2 * nq + 1] - mu) * rs * g2.y + lb2.y, 0.f);
                if (vv) *(__half2*)(out + (size_t)row * 64 + c) = __floats2half2_rn(y0, y1);
            }
        }
    }
}

// ===========================================================================
// 64-ch layers: persistent, barrier-free, paired-uint4 gather (k-perm v2)
// 128 threads, 4 warps, warp = 32 nodes; 3 blocks/SM via launch bounds
// ===========================================================================
constexpr int NOFF_B  = 8192;                // C1 frag tile lives at 0 (4 KB)
constexpr int NSMEM   = NOFF_B + 5 * 8192;   // 49152

template <bool CLS>
__global__ __launch_bounds__(128, 3)
void mesh_fast(const __half* __restrict__ xin, const int* __restrict__ nbr,
               const __half* __restrict__ Wt,          // [64][320] (k-perm2) fp16
               const float* __restrict__ bias, const float* __restrict__ lng,
               const float* __restrict__ lnb,
               const __half* __restrict__ c1t,         // cls frag tile (4 KB)
               const float* __restrict__ cb1,
               const float* __restrict__ cw2, const float* __restrict__ cb2,
               __half* __restrict__ outh, float* __restrict__ outf)
{
    extern __shared__ char smc[];
    const int tid = threadIdx.x, wid = tid >> 5, lane = tid & 31;

    // ---- stage B once: 5 segments, swizzled rows for ldmatrix (40 KB) ----
    for (int j = tid; j < 2560; j += 128) {
        int r = j >> 3, c = j & 7;
        int seg = r >> 6, nrow = r & 63;
        const char* src = (const char*)Wt + (size_t)nrow * 640 + seg * 128 + c * 16;
        char* dst = smc + NOFF_B + seg * 8192;
        *(uint4*)(dst + swz((u32)(nrow * 128 + c * 16))) = *(const uint4*)src;
    }
    if (CLS) {
        for (int i = tid; i < 256; i += 128)
            ((uint4*)smc)[i] = ((const uint4*)c1t)[i];
    }
    __syncthreads();   // the ONLY block barrier

    const int g = lane >> 2, t = lane & 3, t4 = lane >> 3;

    auto bofs = [&](int pb, int k16) -> u32 {
        return swz((u32)(((2 * pb + (t4 >> 1)) * 8 + (lane & 7)) * 128
                         + k16 * 32 + ((t4 & 1) << 4)));
    };

    for (int tile = blockIdx.x; tile < NTILES; tile += gridDim.x) {
        const int node0 = tile * 128;
        // warp covers 32 rows: row-block rb in {0,1}, half hf in {0,1}
        int  rr[4]; bool vv[4];
#pragma unroll
        for (int i = 0; i < 4; i++) {
            int row = node0 + wid * 32 + 16 * (i >> 1) + 8 * (i & 1) + g;
            vv[i] = row < E_NODES;
            rr[i] = vv[i] ? row : 0;
        }

        float acc[2][8][4];
#pragma unroll
        for (int rb = 0; rb < 2; rb++)
#pragma unroll
            for (int q = 0; q < 8; q++)
#pragma unroll
                for (int c = 0; c < 4; c++) acc[rb][q][c] = 0.f;

        auto run_seg = [&](int seg, int k16, const u32* a0, const u32* a1) {
            u32 bh[16];
            u32 bb = s2u(smc + NOFF_B + seg * 8192);
#pragma unroll
            for (int pb = 0; pb < 4; pb++)
                ldmx4(bh + 4 * pb, bb + bofs(pb, k16));
#pragma unroll
            for (int nq = 0; nq < 8; nq++) {
                mma_h(acc[0][nq], a0, bh[2 * nq], bh[2 * nq + 1]);
                mma_h(acc[1][nq], a1, bh[2 * nq], bh[2 * nq + 1]);
            }
        };

        // ---- phase 0: x (seg 0) — one uint4 covers two k16 blocks ----
#pragma unroll
        for (int p = 0; p < 2; p++) {
            const int fo = 32 * p + 8 * t;
            uint4 x00 = *(const uint4*)(xin + (size_t)rr[0] * 64 + fo);
            uint4 x01 = *(const uint4*)(xin + (size_t)rr[1] * 64 + fo);
            uint4 x10 = *(const uint4*)(xin + (size_t)rr[2] * 64 + fo);
            uint4 x11 = *(const uint4*)(xin + (size_t)rr[3] * 64 + fo);
            {
                u32 aA0[4] = {x00.x, x01.x, x00.y, x01.y};
                u32 aA1[4] = {x10.x, x11.x, x10.y, x11.y};
                run_seg(0, 2 * p, aA0, aA1);
            }
            {
                u32 aB0[4] = {x00.z, x01.z, x00.w, x01.w};
                u32 aB1[4] = {x10.z, x11.z, x10.w, x11.w};
                run_seg(0, 2 * p + 1, aB0, aB1);
            }
        }

        // ---- phases 1,2: neighbor pairs (segs 1,2 and 3,4) ----
#pragma unroll
        for (int ph = 0; ph < 2; ph++) {
            const int sd = ph ? 3 : 1;
            int ia[4], ic[4];
#pragma unroll
            for (int i = 0; i < 4; i++) {
                int4 nb = ((const int4*)nbr)[rr[i]];
                ia[i] = ph ? nb.y : nb.x;
                ic[i] = ph ? nb.w : nb.z;
            }
#pragma unroll
            for (int p = 0; p < 2; p++) {
                const int fo = 32 * p + 8 * t;
                uint4 av[4], cv[4];
#pragma unroll
                for (int i = 0; i < 4; i++) {
                    av[i] = *(const uint4*)(xin + (size_t)ia[i] * 64 + fo);
                    cv[i] = *(const uint4*)(xin + (size_t)ic[i] * 64 + fo);
                }
                {
                    u32 dA0[4] = {habsd(av[0].x, cv[0].x), habsd(av[1].x, cv[1].x),
                                  habsd(av[0].y, cv[0].y), habsd(av[1].y, cv[1].y)};
                    u32 dA1[4] = {habsd(av[2].x, cv[2].x), habsd(av[3].x, cv[3].x),
                                  habsd(av[2].y, cv[2].y), habsd(av[3].y, cv[3].y)};
                    run_seg(sd, 2 * p, dA0, dA1);
                }
                {
                    u32 dB0[4] = {habsd(av[0].z, cv[0].z), habsd(av[1].z, cv[1].z),
                                  habsd(av[0].w, cv[0].w), habsd(av[1].w, cv[1].w)};
                    u32 dB1[4] = {habsd(av[2].z, cv[2].z), habsd(av[3].z, cv[3].z),
                                  habsd(av[2].w, cv[2].w), habsd(av[3].w, cv[3].w)};
                    run_seg(sd, 2 * p + 1, dB0, dB1);
                }
                {
                    u32 sA0[4] = {hsum(av[0].x, cv[0].x), hsum(av[1].x, cv[1].x),
                                  hsum(av[0].y, cv[0].y), hsum(av[1].y, cv[1].y)};
                    u32 sA1[4] = {hsum(av[2].x, cv[2].x), hsum(av[3].x, cv[3].x),
                                  hsum(av[2].y, cv[2].y), hsum(av[3].y, cv[3].y)};
                    run_seg(sd + 1, 2 * p, sA0, sA1);
                }
                {
                    u32 sB0[4] = {hsum(av[0].z, cv[0].z), hsum(av[1].z, cv[1].z),
                                  hsum(av[0].w, cv[0].w), hsum(av[1].w, cv[1].w)};
                    u32 sB1[4] = {hsum(av[2].z, cv[2].z), hsum(av[3].z, cv[3].z),
                                  hsum(av[2].w, cv[2].w), hsum(av[3].w, cv[3].w)};
                    run_seg(sd + 1, 2 * p + 1, sB0, sB1);
                }
            }
        }

        // ---- epilogue: bias + LN + ReLU + residual, in registers ----
#pragma unroll
        for (int rb = 0; rb < 2; rb++)
#pragma unroll
        for (int hf = 0; hf < 2; hf++) {
            const int idx = rb * 2 + hf;
            const int row = rr[idx];
            const bool v_ = vv[idx];
            float tv[16];
            float part = 0.f;
#pragma unroll
            for (int nq = 0; nq < 8; nq++) {
                int c = 8 * nq + 2 * t;
                float2 b2 = *(const float2*)(bias + c);
                tv[2 * nq]     = acc[rb][nq][2 * hf]     + b2.x;
                tv[2 * nq + 1] = acc[rb][nq][2 * hf + 1] + b2.y;
                part += tv[2 * nq] + tv[2 * nq + 1];
            }
            part += __shfl_xor_sync(0xFFFFFFFFu, part, 1);
            part += __shfl_xor_sync(0xFFFFFFFFu, part, 2);
            float mu = part * (1.f / 64.f);
            float vp = 0.f;
#pragma unroll
            for (int i = 0; i < 16; i++) { float d = tv[i] - mu; vp += d * d; }
            vp += __shfl_xor_sync(0xFFFFFFFFu, vp, 1);
            vp += __shfl_xor_sync(0xFFFFFFFFu, vp, 2);
            float rsv = rsqrtf(vp * (1.f / 64.f) + 1e-5f);
#pragma unroll
            for (int nq = 0; nq < 8; nq++) {
                int c = 8 * nq + 2 * t;
                float2 g2  = *(const float2*)(lng + c);
                float2 lb2 = *(const float2*)(lnb + c);
                float2 xr  = __half22float2(*(const __half2*)(xin + (size_t)row * 64 + c));
                float y0 = fmaxf((tv[2 * nq]     - mu) * rsv * g2.x + lb2.x, 0.f) + xr.x;
                float y1 = fmaxf((tv[2 * nq + 1] - mu) * rsv * g2.y + lb2.y, 0.f) + xr.y;
                if (!CLS) {
                    if (v_) *(__half2*)(outh + (size_t)row * 64 + c) = __floats2half2_rn(y0, y1);
                } else {
                    acc[rb][nq][2 * hf]     = y0;
                    acc[rb][nq][2 * hf + 1] = y1;
                }
            }
        }

        if (CLS) {
            const u32 c1h = s2u(smc);
#pragma unroll
            for (int rb = 0; rb < 2; rb++) {
                // head GEMM z = y@cw1 + cb1 on HMMA (2-term split), per row-block
                float zacc[4][4];
#pragma unroll
                for (int nq = 0; nq < 4; nq++) {
                    float b0 = __ldg(cb1 + 8 * nq + 2 * t);
                    float b1 = __ldg(cb1 + 8 * nq + 2 * t + 1);
                    zacc[nq][0] = b0; zacc[nq][1] = b1; zacc[nq][2] = b0; zacc[nq][3] = b1;
                }
#pragma unroll
                for (int j = 0; j < 4; j++) {
                    u32 ah[4], al[4];
                    split2h(acc[rb][2 * j][0],     acc[rb][2 * j][1],     ah[0], al[0]);
                    split2h(acc[rb][2 * j][2],     acc[rb][2 * j][3],     ah[1], al[1]);
                    split2h(acc[rb][2 * j + 1][0], acc[rb][2 * j + 1][1], ah[2], al[2]);
                    split2h(acc[rb][2 * j + 1][2], acc[rb][2 * j + 1][3], ah[3], al[3]);
                    u32 bh[8];
#pragma unroll
                    for (int pb = 0; pb < 2; pb++)
                        ldmx4(bh + 4 * pb, c1h + bofs(pb, j));
#pragma unroll
                    for (int nq = 0; nq < 4; nq++) {
                        mma_h(zacc[nq], ah, bh[2 * nq], bh[2 * nq + 1]);
                        mma_h(zacc[nq], al, bh[2 * nq], bh[2 * nq + 1]);
                    }
                }
                float p0 = 0.f, p1 = 0.f;
#pragma unroll
                for (int nq = 0; nq < 4; nq++) {
                    float w0 = __ldg(cw2 + 8 * nq + 2 * t);
                    float w1 = __ldg(cw2 + 8 * nq + 2 * t + 1);
                    p0 += fmaxf(zacc[nq][0], 0.f) * w0 + fmaxf(zacc[nq][1], 0.f) * w1;
                    p1 += fmaxf(zacc[nq][2], 0.f) * w0 + fmaxf(zacc[nq][3], 0.f) * w1;
                }
                p0 += __shfl_xor_sync(0xFFFFFFFFu, p0, 1);
                p0 += __shfl_xor_sync(0xFFFFFFFFu, p0, 2);
                p1 += __shfl_xor_sync(0xFFFFFFFFu, p1, 1);
                p1 += __shfl_xor_sync(0xFFFFFFFFu, p1, 2);
                if (t == 0) {
                    float c2 = __ldg(cb2);
                    if (vv[rb * 2 + 0]) outf[rr[rb * 2 + 0]] = p0 + c2;
                    if (vv[rb * 2 + 1]) outf[rr[rb * 2 + 1]] = p1 + c2;
                }
            }
        }
    }
}

// ---------------------------------------------------------------------------

extern "C" void kernel_launch(void* const* d_in, const int* in_sizes, int n_in,
                              void* d_out, int out_size)
{
    const float* x      = (const float*)d_in[0];
    const int*   nbr    = (const int*)  d_in[1];
    const float* w0     = (const float*)d_in[2];
    const float* b0     = (const float*)d_in[3];
    const float* w_rest = (const float*)d_in[4];
    const float* b_rest = (const float*)d_in[5];
    const float* ln_g   = (const float*)d_in[6];
    const float* ln_b   = (const float*)d_in[7];
    const float* cw1    = (const float*)d_in[8];
    const float* cb1    = (const float*)d_in[9];
    const float* cw2    = (const float*)d_in[10];
    const float* cb2    = (const float*)d_in[11];
    float* out = (float*)d_out;

    __half *bufA, *bufB, *WRp, *C1p;
    u32 *B0p;
    cudaGetSymbolAddress((void**)&bufA, g_bufA);
    cudaGetSymbolAddress((void**)&bufB, g_bufB);
    cudaGetSymbolAddress((void**)&WRp, g_WR);
    cudaGetSymbolAddress((void**)&B0p, g_B0);
    cudaGetSymbolAddress((void**)&C1p, g_C1);

    cudaFuncSetAttribute(mesh_l0, cudaFuncAttributeMaxDynamicSharedMemorySize, SMEM_L0);
    cudaFuncSetAttribute(mesh_fast<false>, cudaFuncAttributeMaxDynamicSharedMemorySize, NSMEM);
    cudaFuncSetAttribute(mesh_fast<true>,  cudaFuncAttributeMaxDynamicSharedMemorySize, NSMEM);

    prep_w<<<240, 256>>>(w0, w_rest, cw1);

    mesh_l0<<<PGRID_L0, 256, SMEM_L0>>>(x, nbr, B0p, b0, ln_g, ln_b, bufA);

    mesh_fast<false><<<PGRID_MID, 128, NSMEM>>>(
        bufA, nbr, WRp, b_rest, ln_g + 64, ln_b + 64,
        nullptr, nullptr, nullptr, nullptr, bufB, nullptr);

    mesh_fast<false><<<PGRID_MID, 128, NSMEM>>>(
        bufB, nbr, WRp + 64 * 320, b_rest + 64, ln_g + 128, ln_b + 128,
        nullptr, nullptr, nullptr, nullptr, bufA, nullptr);

    mesh_fast<true><<<PGRID_MID, 128, NSMEM>>>(
        bufA, nbr, WRp + 2 * 64 * 320, b_rest + 128, ln_g + 192, ln_b + 192,
        C1p, cb1, cw2, cb2, nullptr, out);
}

// round 17
// speedup vs baseline: 1.0847x; 1.0276x over previous
#include <cuda_runtime.h>
#include <cuda_fp16.h>
#include <cstdint>

typedef unsigned int u32;
typedef unsigned long long u64;

#define E_NODES 1000000
#define NTILES ((E_NODES + 127) / 128)
#define PGRID_L0 304
#define PGRID_MID 456

// Scratch activations (fp16) + prepacked weights (alloc-free rule)
__device__ __half g_bufA[(size_t)E_NODES * 64];
__device__ __half g_bufB[(size_t)E_NODES * 64];
__device__ __half g_WR[3 * 64 * 320];                // [l][n][kperm2]  fp16
__device__ __align__(16) u32 g_B0[4 * 8 * 32 * 2];   // l0 frag-packed B (fp16)
__device__ __align__(16) __half g_C1[32 * 64];       // cls W1 frag tile (fp16)

// ---------------------------------------------------------------------------
// helpers
// ---------------------------------------------------------------------------
__device__ __forceinline__ u32 s2u(const void* p) {
    u32 a;
    asm("{.reg .u64 t; cvta.to.shared.u64 t,%1; cvt.u32.u64 %0,t;}" : "=r"(a) : "l"(p));
    return a;
}
__device__ __forceinline__ u32 swz(u32 b) { return b ^ ((b >> 3) & 0x70); }

__device__ __forceinline__ void ldmx4(u32* r, u32 addr) {
    asm volatile("ldmatrix.sync.aligned.m8n8.x4.shared.b16 {%0,%1,%2,%3},[%4];"
                 : "=r"(r[0]), "=r"(r[1]), "=r"(r[2]), "=r"(r[3]) : "r"(addr));
}
__device__ __forceinline__ void mma_h(float* d, const u32* a, u32 b0, u32 b1) {
    asm volatile(
        "mma.sync.aligned.m16n8k16.row.col.f32.f16.f16.f32 "
        "{%0,%1,%2,%3},{%4,%5,%6,%7},{%8,%9},{%0,%1,%2,%3};"
        : "+f"(d[0]), "+f"(d[1]), "+f"(d[2]), "+f"(d[3])
        : "r"(a[0]), "r"(a[1]), "r"(a[2]), "r"(a[3]), "r"(b0), "r"(b1));
}

__device__ __forceinline__ u32 bits2h(__half2 v) {
    u32 u; __builtin_memcpy(&u, &v, 4); return u;
}
__device__ __forceinline__ __half2 h2(u32 u) {
    __half2 v; __builtin_memcpy(&v, &u, 4); return v;
}
__device__ __forceinline__ u32 habsd(u32 a, u32 c) {
    return bits2h(__habs2(__hsub2(h2(a), h2(c))));
}
__device__ __forceinline__ u32 hsum(u32 a, u32 c) {
    return bits2h(__hadd2(h2(a), h2(c)));
}
// split (a,b) fp32 pair into hi/lo fp16x2 packs
__device__ __forceinline__ void split2h(float a, float b, u32& h, u32& l) {
    __half2 hh = __floats2half2_rn(a, b);
    float ra = a - __half2float(__low2half(hh));
    float rb = b - __half2float(__high2half(hh));
    __half2 ll = __floats2half2_rn(ra, rb);
    h = bits2h(hh); l = bits2h(ll);
}
// staging swizzle: row-local byte offset XOR'ed by row for bank spread
__device__ __forceinline__ u32 stsw(int lr, u32 bo) {
    return (u32)(lr * 128) + (bo ^ (u32)((lr & 7) << 4));
}

// ---------------------------------------------------------------------------
// weight prep:
//  - mids: transpose to [n][k], K-PERM v2 (paired-uint4 gather layout)
//  - l0:   frag-packed B (logical k), zero-pad K 55->64
//  - cls:  cw1 -> [32 n][64 k] swizzled frag tile (4 KB)
// ---------------------------------------------------------------------------
__global__ void prep_w(const float* __restrict__ w0, const float* __restrict__ wr,
                       const float* __restrict__ cw1)
{
    int i = blockIdx.x * blockDim.x + threadIdx.x;
    if (i < 1024) {
        int lane = i & 31, nq = (i >> 5) & 7, j = (i >> 8) & 3;
        int g = lane >> 2, t = lane & 3, n = nq * 8 + g;
        int ks[4] = {16 * j + 2 * t, 16 * j + 2 * t + 1,
                     16 * j + 2 * t + 8, 16 * j + 2 * t + 9};
        __half b[4];
#pragma unroll
        for (int q = 0; q < 4; q++) {
            int k = ks[q];
            float v = (k < 55) ? w0[k * 64 + n] : 0.f;
            b[q] = __float2half_rn(v);
        }
        g_B0[i * 2]     = bits2h(__halves2half2(b[0], b[1]));
        g_B0[i * 2 + 1] = bits2h(__halves2half2(b[2], b[3]));
    }
    if (i < 2048) {
        int n = i >> 6, k = i & 63;
        float v = cw1[k * 32 + n];
        *(__half*)((char*)g_C1 + swz((u32)(n * 128 + k * 2))) = __float2half_rn(v);
    }
    if (i < 3 * 64 * 320) {
        int l = i / (64 * 320), r = i % (64 * 320);
        int n = r / 320, k = r % 320;
        float v = wr[(size_t)l * 320 * 64 + (size_t)k * 64 + n];
        // k-perm v2 within each 64-half segment: logical ls -> eff E
        int ls = k & 63;
        int p = ls >> 5, q5 = ls & 31, tt = q5 >> 3, q = q5 & 7;
        int E = (p << 5) + ((q >> 2) << 4) + 2 * tt + (q & 1) + (((q >> 1) & 1) << 3);
        int kp = (k & ~63) | E;
        g_WR[((size_t)l * 64 + n) * 320 + kp] = __float2half_rn(v);
    }
}

// ===========================================================================
// Layer 0 (C=11): persistent, barrier-free, warp-private frag-packed A
// fp32 input -> hi/lo 2-term; fp16 output  (unchanged, proven)
// ===========================================================================
constexpr int L0_B0 = 0;
constexpr int L0_A  = 8192;
constexpr int SMEM_L0 = L0_A + 8 * 4096;  // 40960

__global__ __launch_bounds__(256, 2)
void mesh_l0(const float* __restrict__ xin, const int* __restrict__ nbr,
             const u32* __restrict__ B0, const float* __restrict__ bias,
             const float* __restrict__ lng, const float* __restrict__ lnb,
             __half* __restrict__ out)
{
    extern __shared__ char smc[];
    const int tid = threadIdx.x, wid = tid >> 5, lane = tid & 31;

    for (int i = tid; i < 512; i += 256)
        ((uint4*)(smc + L0_B0))[i] = ((const uint4*)B0)[i];
    __syncthreads();

    char* Aw = smc + L0_A + wid * 4096;
    const int  w     = lane >> 1;
    const int  half_ = lane & 1;
    const int  g = lane >> 2, t = lane & 3;

    for (int tile = blockIdx.x; tile < NTILES; tile += gridDim.x) {
        const int node0 = tile * 128;
        const int node  = node0 + wid * 16 + w;
        const bool valid = node < E_NODES;

        __syncwarp();

        auto wrA = [&](int k, float v) {
            __half hh = __float2half_rn(v);
            __half ll = __float2half_rn(v - __half2float(hh));
            int j = k >> 4, kk = k & 15;
            int pair = kk >> 3, tt = (kk >> 1) & 3, ii = kk & 1;
            int reg = pair * 2 + (w >> 3);
            u32 off = (u32)(((j * 32 + (w & 7) * 4 + tt) << 4) + reg * 4 + ii * 2);
            *(__half*)(Aw + off)        = hh;
            *(__half*)(Aw + 2048 + off) = ll;
        };

        if (valid) {
            int4 nb = ((const int4*)nbr)[node];
            if (half_ == 0) {
                const float* xr = xin + (size_t)node * 11;
                const float* A_ = xin + (size_t)nb.x * 11;
                const float* C_ = xin + (size_t)nb.z * 11;
#pragma unroll
                for (int ch = 0; ch < 11; ch++) {
                    wrA(ch, xr[ch]);
                    float a = A_[ch], c = C_[ch];
                    wrA(11 + ch, fabsf(a - c));
                    wrA(22 + ch, a + c);
                }
            } else {
                const float* B_ = xin + (size_t)nb.y * 11;
                const float* D_ = xin + (size_t)nb.w * 11;
#pragma unroll
                for (int ch = 0; ch < 11; ch++) {
                    float b = B_[ch], d = D_[ch];
                    wrA(33 + ch, fabsf(b - d));
                    wrA(44 + ch, b + d);
                }
#pragma unroll
                for (int k = 55; k < 64; k++) wrA(k, 0.f);
            }
        }
        __syncwarp();

        float acc[8][4];
#pragma unroll
        for (int q = 0; q < 8; q++)
#pragma unroll
            for (int c = 0; c < 4; c++) acc[q][c] = 0.f;

#pragma unroll
        for (int j = 0; j < 4; j++) {
            uint4 avh = *(const uint4*)(Aw + (j * 32 + lane) * 16);
            uint4 avl = *(const uint4*)(Aw + 2048 + (j * 32 + lane) * 16);
            u32 ah[4] = {avh.x, avh.y, avh.z, avh.w};
            u32 al[4] = {avl.x, avl.y, avl.z, avl.w};
#pragma unroll
            for (int nq = 0; nq < 8; nq++) {
                uint2 bh = *(const uint2*)(smc + L0_B0 + (size_t)((j * 8 + nq) * 32 + lane) * 8);
                mma_h(acc[nq], ah, bh.x, bh.y);
                mma_h(acc[nq], al, bh.x, bh.y);
            }
        }

#pragma unroll
        for (int hf = 0; hf < 2; hf++) {
            int row = node0 + wid * 16 + g + 8 * hf;
            bool vv = row < E_NODES;
            float tv[16];
            float part = 0.f;
#pragma unroll
            for (int nq = 0; nq < 8; nq++) {
                int c = 8 * nq + 2 * t;
                float2 b2 = *(const float2*)(bias + c);
                tv[2 * nq]     = acc[nq][2 * hf]     + b2.x;
                tv[2 * nq + 1] = acc[nq][2 * hf + 1] + b2.y;
                part += tv[2 * nq] + tv[2 * nq + 1];
            }
            part += __shfl_xor_sync(0xFFFFFFFFu, part, 1);
            part += __shfl_xor_sync(0xFFFFFFFFu, part, 2);
            float mu = part * (1.f / 64.f);
            float vp = 0.f;
#pragma unroll
            for (int i = 0; i < 16; i++) { float d = tv[i] - mu; vp += d * d; }
            vp += __shfl_xor_sync(0xFFFFFFFFu, vp, 1);
            vp += __shfl_xor_sync(0xFFFFFFFFu, vp, 2);
            float rs = rsqrtf(vp * (1.f / 64.f) + 1e-5f);
#pragma unroll
            for (int nq = 0; nq < 8; nq++) {
                int c = 8 * nq + 2 * t;
                float2 g2  = *(const float2*)(lng + c);
                float2 lb2 = *(const float2*)(lnb + c);
                float y0 = fmaxf((tv[2 * nq]     - mu) * rs * g2.x + lb2.x, 0.f);
                float y1 = fmaxf((tv[2 * nq + 1] - mu) * rs * g2.y + lb2.y, 0.f);
                if (vv) *(__half2*)(out + (size_t)row * 64 + c) = __floats2half2_rn(y0, y1);
            }
        }
    }
}

// ===========================================================================
// 64-ch layers: persistent, barrier-free, paired-uint4 gather (k-perm v2)
// 128 threads, 4 warps, warp = 32 nodes; 3 blocks/SM
// epilogue via warp-private swizzled smem stage: residual reuse + STG.128 out
// ===========================================================================
constexpr int NOFF_B  = 8192;                // C1 frag tile lives at 0 (4 KB)
constexpr int NOFF_ST = NOFF_B + 5 * 8192;   // 49152: 4 warps x 4 KB stage
constexpr int NSMEM   = NOFF_ST + 4 * 4096;  // 65536

template <bool CLS>
__global__ __launch_bounds__(128, 3)
void mesh_fast(const __half* __restrict__ xin, const int* __restrict__ nbr,
               const __half* __restrict__ Wt,          // [64][320] (k-perm2) fp16
               const float* __restrict__ bias, const float* __restrict__ lng,
               const float* __restrict__ lnb,
               const __half* __restrict__ c1t,         // cls frag tile (4 KB)
               const float* __restrict__ cb1,
               const float* __restrict__ cw2, const float* __restrict__ cb2,
               __half* __restrict__ outh, float* __restrict__ outf)
{
    extern __shared__ char smc[];
    const int tid = threadIdx.x, wid = tid >> 5, lane = tid & 31;

    // ---- stage B once: 5 segments, swizzled rows for ldmatrix (40 KB) ----
    for (int j = tid; j < 2560; j += 128) {
        int r = j >> 3, c = j & 7;
        int seg = r >> 6, nrow = r & 63;
        const char* src = (const char*)Wt + (size_t)nrow * 640 + seg * 128 + c * 16;
        char* dst = smc + NOFF_B + seg * 8192;
        *(uint4*)(dst + swz((u32)(nrow * 128 + c * 16))) = *(const uint4*)src;
    }
    if (CLS) {
        for (int i = tid; i < 256; i += 128)
            ((uint4*)smc)[i] = ((const uint4*)c1t)[i];
    }
    __syncthreads();   // the ONLY block barrier

    const int g = lane >> 2, t = lane & 3, t4 = lane >> 3;
    char* stw = smc + NOFF_ST + wid * 4096;   // warp-private stage (32 rows x 128B)

    auto bofs = [&](int pb, int k16) -> u32 {
        return swz((u32)(((2 * pb + (t4 >> 1)) * 8 + (lane & 7)) * 128
                         + k16 * 32 + ((t4 & 1) << 4)));
    };

    for (int tile = blockIdx.x; tile < NTILES; tile += gridDim.x) {
        const int node0 = tile * 128;
        int  rr[4]; bool vv[4];
#pragma unroll
        for (int i = 0; i < 4; i++) {
            int row = node0 + wid * 32 + 16 * (i >> 1) + 8 * (i & 1) + g;
            vv[i] = row < E_NODES;
            rr[i] = vv[i] ? row : 0;
        }

        float acc[2][8][4];
#pragma unroll
        for (int rb = 0; rb < 2; rb++)
#pragma unroll
            for (int q = 0; q < 8; q++)
#pragma unroll
                for (int c = 0; c < 4; c++) acc[rb][q][c] = 0.f;

        auto run_seg = [&](int seg, int k16, const u32* a0, const u32* a1) {
            u32 bh[16];
            u32 bb = s2u(smc + NOFF_B + seg * 8192);
#pragma unroll
            for (int pb = 0; pb < 4; pb++)
                ldmx4(bh + 4 * pb, bb + bofs(pb, k16));
#pragma unroll
            for (int nq = 0; nq < 8; nq++) {
                mma_h(acc[0][nq], a0, bh[2 * nq], bh[2 * nq + 1]);
                mma_h(acc[1][nq], a1, bh[2 * nq], bh[2 * nq + 1]);
            }
        };

        __syncwarp();   // prior-tile stage readout complete before overwrite

        // ---- phase 0: x (seg 0) — uint4 covers two k16 blocks; stage x ----
#pragma unroll
        for (int p = 0; p < 2; p++) {
            const int fo = 32 * p + 8 * t;
            uint4 x00 = *(const uint4*)(xin + (size_t)rr[0] * 64 + fo);
            uint4 x01 = *(const uint4*)(xin + (size_t)rr[1] * 64 + fo);
            uint4 x10 = *(const uint4*)(xin + (size_t)rr[2] * 64 + fo);
            uint4 x11 = *(const uint4*)(xin + (size_t)rr[3] * 64 + fo);
            const u32 bo = (u32)(64 * p + 16 * t);
            *(uint4*)(stw + stsw(g,      bo)) = x00;
            *(uint4*)(stw + stsw(g + 8,  bo)) = x01;
            *(uint4*)(stw + stsw(g + 16, bo)) = x10;
            *(uint4*)(stw + stsw(g + 24, bo)) = x11;
            {
                u32 aA0[4] = {x00.x, x01.x, x00.y, x01.y};
                u32 aA1[4] = {x10.x, x11.x, x10.y, x11.y};
                run_seg(0, 2 * p, aA0, aA1);
            }
            {
                u32 aB0[4] = {x00.z, x01.z, x00.w, x01.w};
                u32 aB1[4] = {x10.z, x11.z, x10.w, x11.w};
                run_seg(0, 2 * p + 1, aB0, aB1);
            }
        }

        // ---- phases 1,2: neighbor pairs (segs 1,2 and 3,4) ----
#pragma unroll
        for (int ph = 0; ph < 2; ph++) {
            const int sd = ph ? 3 : 1;
            int ia[4], ic[4];
#pragma unroll
            for (int i = 0; i < 4; i++) {
                int4 nb = ((const int4*)nbr)[rr[i]];
                ia[i] = ph ? nb.y : nb.x;
                ic[i] = ph ? nb.w : nb.z;
            }
#pragma unroll
            for (int p = 0; p < 2; p++) {
                const int fo = 32 * p + 8 * t;
                uint4 av[4], cv[4];
#pragma unroll
                for (int i = 0; i < 4; i++) {
                    av[i] = *(const uint4*)(xin + (size_t)ia[i] * 64 + fo);
                    cv[i] = *(const uint4*)(xin + (size_t)ic[i] * 64 + fo);
                }
                {
                    u32 dA0[4] = {habsd(av[0].x, cv[0].x), habsd(av[1].x, cv[1].x),
                                  habsd(av[0].y, cv[0].y), habsd(av[1].y, cv[1].y)};
                    u32 dA1[4] = {habsd(av[2].x, cv[2].x), habsd(av[3].x, cv[3].x),
                                  habsd(av[2].y, cv[2].y), habsd(av[3].y, cv[3].y)};
                    run_seg(sd, 2 * p, dA0, dA1);
                }
                {
                    u32 dB0[4] = {habsd(av[0].z, cv[0].z), habsd(av[1].z, cv[1].z),
                                  habsd(av[0].w, cv[0].w), habsd(av[1].w, cv[1].w)};
                    u32 dB1[4] = {habsd(av[2].z, cv[2].z), habsd(av[3].z, cv[3].z),
                                  habsd(av[2].w, cv[2].w), habsd(av[3].w, cv[3].w)};
                    run_seg(sd, 2 * p + 1, dB0, dB1);
                }
                {
                    u32 sA0[4] = {hsum(av[0].x, cv[0].x), hsum(av[1].x, cv[1].x),
                                  hsum(av[0].y, cv[0].y), hsum(av[1].y, cv[1].y)};
                    u32 sA1[4] = {hsum(av[2].x, cv[2].x), hsum(av[3].x, cv[3].x),
                                  hsum(av[2].y, cv[2].y), hsum(av[3].y, cv[3].y)};
                    run_seg(sd + 1, 2 * p, sA0, sA1);
                }
                {
                    u32 sB0[4] = {hsum(av[0].z, cv[0].z), hsum(av[1].z, cv[1].z),
                                  hsum(av[0].w, cv[0].w), hsum(av[1].w, cv[1].w)};
                    u32 sB1[4] = {hsum(av[2].z, cv[2].z), hsum(av[3].z, cv[3].z),
                                  hsum(av[2].w, cv[2].w), hsum(av[3].w, cv[3].w)};
                    run_seg(sd + 1, 2 * p + 1, sB0, sB1);
                }
            }
        }

        __syncwarp();   // x staging visible to in-warp readers

        // ---- hoisted LN params (tile-invariant) ----
        float2 b2v[8], g2v[8], l2v[8];
#pragma unroll
        for (int nq = 0; nq < 8; nq++) {
            int c = 8 * nq + 2 * t;
            b2v[nq] = *(const float2*)(bias + c);
            g2v[nq] = *(const float2*)(lng + c);
            l2v[nq] = *(const float2*)(lnb + c);
        }

        // ---- epilogue: bias + LN + ReLU + residual (stage), y -> stage ----
#pragma unroll
        for (int rb = 0; rb < 2; rb++)
#pragma unroll
        for (int hf = 0; hf < 2; hf++) {
            const int lr = 16 * rb + 8 * hf + g;
            float tv[16];
            float part = 0.f;
#pragma unroll
            for (int nq = 0; nq < 8; nq++) {
                tv[2 * nq]     = acc[rb][nq][2 * hf]     + b2v[nq].x;
                tv[2 * nq + 1] = acc[rb][nq][2 * hf + 1] + b2v[nq].y;
                part += tv[2 * nq] + tv[2 * nq + 1];
            }
            part += __shfl_xor_sync(0xFFFFFFFFu, part, 1);
            part += __shfl_xor_sync(0xFFFFFFFFu, part, 2);
            float mu = part * (1.f / 64.f);
            float vp = 0.f;
#pragma unroll
            for (int i = 0; i < 16; i++) { float d = tv[i] - mu; vp += d * d; }
            vp += __shfl_xor_sync(0xFFFFFFFFu, vp, 1);
            vp += __shfl_xor_sync(0xFFFFFFFFu, vp, 2);
            float rsv = rsqrtf(vp * (1.f / 64.f) + 1e-5f);
#pragma unroll
            for (int nq = 0; nq < 8; nq++) {
                u32 so = stsw(lr, (u32)(16 * nq + 4 * t));
                float2 xr = __half22float2(*(const __half2*)(stw + so));
                float y0 = fmaxf((tv[2 * nq]     - mu) * rsv * g2v[nq].x + l2v[nq].x, 0.f) + xr.x;
                float y1 = fmaxf((tv[2 * nq + 1] - mu) * rsv * g2v[nq].y + l2v[nq].y, 0.f) + xr.y;
                if (!CLS) {
                    *(__half2*)(stw + so) = __floats2half2_rn(y0, y1);
                } else {
                    acc[rb][nq][2 * hf]     = y0;
                    acc[rb][nq][2 * hf + 1] = y1;
                }
            }
        }

        if (!CLS) {
            __syncwarp();   // y staging visible
            // coalesced readout: 8 x (LDS.128 + STG.128), 4 rows per instr
#pragma unroll
            for (int s = 0; s < 8; s++) {
                int row = 4 * s + (lane >> 3);
                u32 bo = (u32)((lane & 7) * 16);
                uint4 v = *(const uint4*)(stw + stsw(row, bo));
                int grow = node0 + wid * 32 + row;
                if (grow < E_NODES)
                    *(uint4*)((char*)(outh + (size_t)grow * 64) + (lane & 7) * 16) = v;
            }
        } else {
            const u32 c1h = s2u(smc);
#pragma unroll
            for (int rb = 0; rb < 2; rb++) {
                float zacc[4][4];
#pragma unroll
                for (int nq = 0; nq < 4; nq++) {
                    float b0 = __ldg(cb1 + 8 * nq + 2 * t);
                    float b1 = __ldg(cb1 + 8 * nq + 2 * t + 1);
                    zacc[nq][0] = b0; zacc[nq][1] = b1; zacc[nq][2] = b0; zacc[nq][3] = b1;
                }
#pragma unroll
                for (int j = 0; j < 4; j++) {
                    u32 ah[4], al[4];
                    split2h(acc[rb][2 * j][0],     acc[rb][2 * j][1],     ah[0], al[0]);
                    split2h(acc[rb][2 * j][2],     acc[rb][2 * j][3],     ah[1], al[1]);
                    split2h(acc[rb][2 * j + 1][0], acc[rb][2 * j + 1][1], ah[2], al[2]);
                    split2h(acc[rb][2 * j + 1][2], acc[rb][2 * j + 1][3], ah[3], al[3]);
                    u32 bh[8];
#pragma unroll
                    for (int pb = 0; pb < 2; pb++)
                        ldmx4(bh + 4 * pb, c1h + bofs(pb, j));
#pragma unroll
                    for (int nq = 0; nq < 4; nq++) {
                        mma_h(zacc[nq], ah, bh[2 * nq], bh[2 * nq + 1]);
                        mma_h(zacc[nq], al, bh[2 * nq], bh[2 * nq + 1]);
                    }
                }
                float p0 = 0.f, p1 = 0.f;
#pragma unroll
                for (int nq = 0; nq < 4; nq++) {
                    float w0 = __ldg(cw2 + 8 * nq + 2 * t);
                    float w1 = __ldg(cw2 + 8 * nq + 2 * t + 1);
                    p0 += fmaxf(zacc[nq][0], 0.f) * w0 + fmaxf(zacc[nq][1], 0.f) * w1;
                    p1 += fmaxf(zacc[nq][2], 0.f) * w0 + fmaxf(zacc[nq][3], 0.f) * w1;
                }
                p0 += __shfl_xor_sync(0xFFFFFFFFu, p0, 1);
                p0 += __shfl_xor_sync(0xFFFFFFFFu, p0, 2);
                p1 += __shfl_xor_sync(0xFFFFFFFFu, p1, 1);
                p1 += __shfl_xor_sync(0xFFFFFFFFu, p1, 2);
                if (t == 0) {
                    float c2 = __ldg(cb2);
                    if (vv[rb * 2 + 0]) outf[rr[rb * 2 + 0]] = p0 + c2;
                    if (vv[rb * 2 + 1]) outf[rr[rb * 2 + 1]] = p1 + c2;
                }
            }
        }
    }
}

// ---------------------------------------------------------------------------

extern "C" void kernel_launch(void* const* d_in, const int* in_sizes, int n_in,
                              void* d_out, int out_size)
{
    const float* x      = (const float*)d_in[0];
    const int*   nbr    = (const int*)  d_in[1];
    const float* w0     = (const float*)d_in[2];
    const float* b0     = (const float*)d_in[3];
    const float* w_rest = (const float*)d_in[4];
    const float* b_rest = (const float*)d_in[5];
    const float* ln_g   = (const float*)d_in[6];
    const float* ln_b   = (const float*)d_in[7];
    const float* cw1    = (const float*)d_in[8];
    const float* cb1    = (const float*)d_in[9];
    const float* cw2    = (const float*)d_in[10];
    const float* cb2    = (const float*)d_in[11];
    float* out = (float*)d_out;

    __half *bufA, *bufB, *WRp, *C1p;
    u32 *B0p;
    cudaGetSymbolAddress((void**)&bufA, g_bufA);
    cudaGetSymbolAddress((void**)&bufB, g_bufB);
    cudaGetSymbolAddress((void**)&WRp, g_WR);
    cudaGetSymbolAddress((void**)&B0p, g_B0);
    cudaGetSymbolAddress((void**)&C1p, g_C1);

    cudaFuncSetAttribute(mesh_l0, cudaFuncAttributeMaxDynamicSharedMemorySize, SMEM_L0);
    cudaFuncSetAttribute(mesh_fast<false>, cudaFuncAttributeMaxDynamicSharedMemorySize, NSMEM);
    cudaFuncSetAttribute(mesh_fast<true>,  cudaFuncAttributeMaxDynamicSharedMemorySize, NSMEM);

    prep_w<<<240, 256>>>(w0, w_rest, cw1);

    mesh_l0<<<PGRID_L0, 256, SMEM_L0>>>(x, nbr, B0p, b0, ln_g, ln_b, bufA);

    mesh_fast<false><<<PGRID_MID, 128, NSMEM>>>(
        bufA, nbr, WRp, b_rest, ln_g + 64, ln_b + 64,
        nullptr, nullptr, nullptr, nullptr, bufB, nullptr);

    mesh_fast<false><<<PGRID_MID, 128, NSMEM>>>(
        bufB, nbr, WRp + 64 * 320, b_rest + 64, ln_g + 128, ln_b + 128,
        nullptr, nullptr, nullptr, nullptr, bufA, nullptr);

    mesh_fast<true><<<PGRID_MID, 128, NSMEM>>>(
        bufA, nbr, WRp + 2 * 64 * 320, b_rest + 128, ln_g + 192, ln_b + 192,
        C1p, cb1, cw2, cb2, nullptr, out);
}